// round 10
// baseline (speedup 1.0000x reference)
#include <cuda_runtime.h>
#include <cfloat>
#include <math.h>

#define Cdim 256
#define Hdim 128
#define Wdim 128
#define HW   16384
#define Bdim 8
#define NTT  512        // tiles per batch: (row, quarter), 32 px each

// ---------------- scratch (device globals) ----------------
__device__ float g_up[16*Cdim];          // partial u
__device__ float g_u[Cdim];              // v_w^T w3
__device__ float g_t3bias;               // w3 . v_b
__device__ float g_t3s[Bdim*HW];         // t3 per pixel
__device__ float g_Mt[Bdim*NTT];
__device__ float g_Zt[Bdim*NTT];
__device__ float g_hpm[Bdim*NTT];        // per-tile h max partial
__device__ float g_hps[Bdim*NTT];        // per-tile h sum partial
__device__ float g_wpm[Bdim*NTT*32];     // per-tile column max partial
__device__ float g_wps[Bdim*NTT*32];     // per-tile column sum partial
__device__ float g_xkp[Bdim*NTT*Cdim];   // per-tile unnormalized xk partial
__device__ float g_xk[Bdim*Cdim];        // combined xk
__device__ float g_ah[Bdim*Hdim];
__device__ float g_aw[Bdim*Wdim];
__device__ float g_cf[Bdim*Cdim];        // channel_fea

// ---------------- helpers ----------------
__device__ __forceinline__ float warpMax(float v){
  #pragma unroll
  for (int o=16;o;o>>=1) v = fmaxf(v, __shfl_xor_sync(0xffffffffu, v, o));
  return v;
}
__device__ __forceinline__ float warpSum(float v){
  #pragma unroll
  for (int o=16;o;o>>=1) v += __shfl_xor_sync(0xffffffffu, v, o);
  return v;
}
__device__ __forceinline__ float sigmoidf_(float x){ return 1.f/(1.f+expf(-x)); }

// ---------------- K0a: partial u (16 blocks) ----------------
__global__ __launch_bounds__(256)
void k0a(const float* __restrict__ vw, const float* __restrict__ w3){
  const int g = blockIdx.x, t = threadIdx.x;
  float u = 0.f;
  #pragma unroll
  for (int oo=0;oo<16;oo++){
    int o = 16*g + oo;
    u = fmaf(__ldg(&w3[o]), vw[o*Cdim + t], u);
  }
  g_up[g*Cdim + t] = u;
}

// ---------------- K0b: combine u + parallel t3bias ----------------
__global__ __launch_bounds__(256)
void k0b(const float* __restrict__ vb, const float* __restrict__ w3){
  const int t = threadIdx.x, warp = t>>5, lane = t&31;
  __shared__ float s_red[8];
  float u = 0.f;
  #pragma unroll
  for (int g=0;g<16;g++) u += g_up[g*Cdim + t];
  g_u[t] = u;
  float p = w3[t]*vb[t];
  p = warpSum(p);
  if (lane==0) s_red[warp] = p;
  __syncthreads();
  if (t==0){
    float tb = 0.f;
    #pragma unroll
    for (int r=0;r<8;r++) tb += s_red[r];
    g_t3bias = tb;
  }
}

// ---------------- Kd: dummy (aligns K1 to profiled launch slot #4) --------
__global__ void kdummy(){ }

// ---------------- K1: fused main pass, x read ONCE, tile in registers ------
// grid (NTT, Bdim), 256 thr. Tile = 32 px (quarter row) x 256 channels.
// Thread: f4i = t&7 (8 f4 = 32 px), cg = t>>3 (32 groups of 8 channels).
__global__ __launch_bounds__(256)
void k1_main(const float* __restrict__ x, const float* __restrict__ kwp,
             const float* __restrict__ kbp,
             const float* __restrict__ w1, const float* __restrict__ b1){
  __shared__ float  s_kw[Cdim], s_u[Cdim];
  __shared__ float4 s_rlp[64], s_rtp[64], s_rpm[64], s_rps[64];  // 4 KB
  __shared__ float4 s_e[8];
  __shared__ float  s_acc[256*9];                                // 9 KB

  const int jt = blockIdx.x, b = blockIdx.y;
  const int row = jt>>2, q = jt&3;
  const int t = threadIdx.x, w = t>>5, lane = t&31;
  const int f4i = t&7, cg = t>>3;

  s_kw[t] = kwp[t];
  s_u[t]  = g_u[t];
  __syncthreads();

  const float* xb = x + ((size_t)(b*Cdim + 8*cg))*HW + row*Wdim + q*32 + 4*f4i;

  // ---- pass A: load 8 channels into registers + accumulate partials ----
  float4 xv[8];
  #pragma unroll
  for (int k=0;k<8;k++) xv[k] = *(const float4*)(xb + (size_t)k*HW);

  float4 aL = make_float4(0,0,0,0), aT = make_float4(0,0,0,0);
  float4 pm = make_float4(-FLT_MAX,-FLT_MAX,-FLT_MAX,-FLT_MAX);
  float4 ps = make_float4(0,0,0,0);
  #pragma unroll
  for (int k=0;k<8;k++){
    float4 v = xv[k];
    int c = 8*cg + k;
    float kw = s_kw[c], uc = s_u[c];
    aL.x = fmaf(kw, v.x, aL.x); aL.y = fmaf(kw, v.y, aL.y);
    aL.z = fmaf(kw, v.z, aL.z); aL.w = fmaf(kw, v.w, aL.w);
    aT.x = fmaf(uc, v.x, aT.x); aT.y = fmaf(uc, v.y, aT.y);
    aT.z = fmaf(uc, v.z, aT.z); aT.w = fmaf(uc, v.w, aT.w);
    pm.x = fmaxf(pm.x, v.x); pm.y = fmaxf(pm.y, v.y);
    pm.z = fmaxf(pm.z, v.z); pm.w = fmaxf(pm.w, v.w);
    ps.x += v.x; ps.y += v.y; ps.z += v.z; ps.w += v.w;
  }

  // ---- intra-warp reduce over the 4 channel-group slots (lane bits 3,4) ----
  #pragma unroll
  for (int o=8;o<=16;o<<=1){
    aL.x += __shfl_xor_sync(~0u, aL.x, o); aL.y += __shfl_xor_sync(~0u, aL.y, o);
    aL.z += __shfl_xor_sync(~0u, aL.z, o); aL.w += __shfl_xor_sync(~0u, aL.w, o);
    aT.x += __shfl_xor_sync(~0u, aT.x, o); aT.y += __shfl_xor_sync(~0u, aT.y, o);
    aT.z += __shfl_xor_sync(~0u, aT.z, o); aT.w += __shfl_xor_sync(~0u, aT.w, o);
    pm.x = fmaxf(pm.x, __shfl_xor_sync(~0u, pm.x, o));
    pm.y = fmaxf(pm.y, __shfl_xor_sync(~0u, pm.y, o));
    pm.z = fmaxf(pm.z, __shfl_xor_sync(~0u, pm.z, o));
    pm.w = fmaxf(pm.w, __shfl_xor_sync(~0u, pm.w, o));
    ps.x += __shfl_xor_sync(~0u, ps.x, o); ps.y += __shfl_xor_sync(~0u, ps.y, o);
    ps.z += __shfl_xor_sync(~0u, ps.z, o); ps.w += __shfl_xor_sync(~0u, ps.w, o);
  }
  if (lane < 8){
    s_rlp[w*8+lane] = aL; s_rtp[w*8+lane] = aT;
    s_rpm[w*8+lane] = pm; s_rps[w*8+lane] = ps;
  }
  __syncthreads();

  // ---- warp 0: per-pixel combine, t3, pools, softmax stats ----
  if (w == 0){
    const bool valid = (lane < 8);
    float hm = -FLT_MAX, hs = 0.f, lm = -FLT_MAX;
    float4 l = make_float4(0,0,0,0);
    if (valid){
      float4 tv = make_float4(0,0,0,0);
      float4 cm = make_float4(-FLT_MAX,-FLT_MAX,-FLT_MAX,-FLT_MAX);
      float4 cs = make_float4(0,0,0,0);
      #pragma unroll
      for (int i=0;i<8;i++){
        float4 a = s_rlp[i*8+lane], bb = s_rtp[i*8+lane];
        float4 m = s_rpm[i*8+lane], ss = s_rps[i*8+lane];
        l.x += a.x; l.y += a.y; l.z += a.z; l.w += a.w;
        tv.x += bb.x; tv.y += bb.y; tv.z += bb.z; tv.w += bb.w;
        cm.x = fmaxf(cm.x,m.x); cm.y = fmaxf(cm.y,m.y);
        cm.z = fmaxf(cm.z,m.z); cm.w = fmaxf(cm.w,m.w);
        cs.x += ss.x; cs.y += ss.y; cs.z += ss.z; cs.w += ss.w;
      }
      const float kb = kbp[0], tb = g_t3bias;
      l.x += kb; l.y += kb; l.z += kb; l.w += kb;
      tv.x += tb; tv.y += tb; tv.z += tb; tv.w += tb;
      *(float4*)(g_t3s + (size_t)b*HW + row*Wdim + q*32 + 4*lane) = tv;
      *(float4*)(g_wpm + ((size_t)(b*NTT+jt))*32 + 4*lane) = cm;
      *(float4*)(g_wps + ((size_t)(b*NTT+jt))*32 + 4*lane) = cs;
      hm = fmaxf(fmaxf(cm.x,cm.y), fmaxf(cm.z,cm.w));
      hs = cs.x+cs.y+cs.z+cs.w;
      lm = fmaxf(fmaxf(l.x,l.y), fmaxf(l.z,l.w));
    }
    float M  = warpMax(lm);
    float hM = warpMax(hm);
    float hS = warpSum(hs);
    float4 e = make_float4(0,0,0,0);
    if (valid){
      e.x = expf(l.x-M); e.y = expf(l.y-M); e.z = expf(l.z-M); e.w = expf(l.w-M);
      s_e[lane] = e;
    }
    float z = warpSum(e.x+e.y+e.z+e.w);
    if (lane==0){
      g_Mt[b*NTT+jt] = M; g_Zt[b*NTT+jt] = z;
      g_hpm[b*NTT+jt] = hM; g_hps[b*NTT+jt] = hS;
    }
  }
  __syncthreads();

  // ---- pass B: xk partials from registers; transpose-reduce ----
  float4 ev = s_e[f4i];
  #pragma unroll
  for (int k=0;k<8;k++){
    int c = 8*cg + k;
    float4 v = xv[k];
    float acc = v.x*ev.x + v.y*ev.y;
    acc = fmaf(v.z, ev.z, acc); acc = fmaf(v.w, ev.w, acc);
    s_acc[c*9 + f4i] = acc;
  }
  __syncthreads();
  float xk = 0.f;
  #pragma unroll
  for (int i=0;i<8;i++) xk += s_acc[t*9 + i];
  g_xkp[((size_t)(b*NTT+jt))*Cdim + t] = xk;
}

// ---------------- K2b: attentions, fully coalesced ----------------
// grid (Bdim), 384 thr. Threads 0..255: w-pools (col(f)=f&127 invariant
// under f = t + 256*i). Threads 256..383: h rows.
__global__ __launch_bounds__(384)
void k2b_attn(const float* __restrict__ w1, const float* __restrict__ b1,
              const float* __restrict__ w2, const float* __restrict__ b2){
  const int b = blockIdx.x, t = threadIdx.x;
  __shared__ float s_m[256], s_s[256];
  if (t < 256){
    const size_t base = (size_t)b*NTT*32;
    float m = -FLT_MAX, s = 0.f;
    #pragma unroll 16
    for (int i=0;i<64;i++){
      size_t idx = base + t + 256*i;
      m = fmaxf(m, g_wpm[idx]);
      s += g_wps[idx];
    }
    s_m[t] = m; s_s[t] = s;
  }
  __syncthreads();
  if (t < 128){
    float m = fmaxf(s_m[t], s_m[t+128]);
    float s = s_s[t] + s_s[t+128];
    g_aw[b*Wdim + t] = sigmoidf_(w2[0]*m + w2[1]*(s*(1.f/32768.f)) + b2[0]);
  } else if (t >= 256){
    int r = t - 256;
    const float* hp = g_hpm + b*NTT + 4*r;
    const float* sp = g_hps + b*NTT + 4*r;
    float m = fmaxf(fmaxf(hp[0],hp[1]), fmaxf(hp[2],hp[3]));
    float s = sp[0]+sp[1]+sp[2]+sp[3];
    g_ah[b*Hdim + r] = sigmoidf_(w1[0]*m + w1[1]*(s*(1.f/32768.f)) + b1[0]);
  }
}

// ---------------- K2c: alpha + xk combine ----------------
// grid (Bdim, 8), 256 thr. Block covers 32 channels x all 512 tiles.
__global__ __launch_bounds__(256)
void k2c_xk(){
  const int b = blockIdx.x, cg = blockIdx.y;
  const int t = threadIdx.x, warp = t>>5, lane = t&31;
  const int jsub = t>>5, c32 = t&31;
  __shared__ float s_alpha[NTT], s_red[8], s_part[8][33];
  __shared__ float sM, sZ;

  // alpha over 512 tiles (each thread covers 2)
  float m0 = g_Mt[b*NTT + t], m1 = g_Mt[b*NTT + 256 + t];
  float m = fmaxf(m0, m1);
  float mm = warpMax(m);
  if (lane==0) s_red[warp] = mm;
  __syncthreads();
  if (t==0){
    float M = s_red[0];
    #pragma unroll
    for (int r=1;r<8;r++) M = fmaxf(M, s_red[r]);
    sM = M;
  }
  __syncthreads();
  float ze = g_Zt[b*NTT + t]*expf(m0 - sM) + g_Zt[b*NTT + 256 + t]*expf(m1 - sM);
  float zz = warpSum(ze);
  if (lane==0) s_red[warp] = zz;
  __syncthreads();
  if (t==0){
    float Z = 0.f;
    #pragma unroll
    for (int r=0;r<8;r++) Z += s_red[r];
    sZ = Z;
  }
  __syncthreads();
  s_alpha[t]       = expf(m0 - sM)/sZ;
  s_alpha[256 + t] = expf(m1 - sM)/sZ;
  __syncthreads();

  const int c = cg*32 + c32;
  float acc = 0.f;
  #pragma unroll 8
  for (int k=0;k<64;k++){
    int j = jsub + 8*k;
    acc = fmaf(g_xkp[((size_t)(b*NTT+j))*Cdim + c], s_alpha[j], acc);
  }
  s_part[jsub][c32] = acc;
  __syncthreads();
  if (t < 32){
    float xk = 0.f;
    #pragma unroll
    for (int r=0;r<8;r++) xk += s_part[r][t];
    g_xk[b*Cdim + cg*32 + t] = xk;
  }
}

// ---------------- K2d: cf = vw @ xk + vb ----------------
// grid (Bdim, 8), 256 thr. Block: 32 outputs, 8 threads each.
__global__ __launch_bounds__(256)
void k2d_cf(const float* __restrict__ vw, const float* __restrict__ vb){
  const int b = blockIdx.x, tg = blockIdx.y;
  const int t = threadIdx.x;
  const int to = t>>3, gg = t&7;
  __shared__ float s_xk[Cdim], s_part[32][9];
  if (t < Cdim) s_xk[t] = g_xk[b*Cdim + t];
  __syncthreads();
  const int tout = tg*32 + to;
  float acc = 0.f;
  #pragma unroll
  for (int cc=0;cc<32;cc++){
    int c = gg*32 + cc;
    acc = fmaf(vw[tout*Cdim + c], s_xk[c], acc);
  }
  s_part[to][gg] = acc;
  __syncthreads();
  if (t < 32){
    float cf = vb[tg*32 + t];
    #pragma unroll
    for (int r=0;r<8;r++) cf += s_part[t][r];
    g_cf[b*Cdim + tg*32 + t] = cf;
  }
}

// ---------------- K5: epilogue (computes s inline; streaming hints) --------
// grid (64, Bdim), 256 thr. Block: all 256 channels x 256 px (2 rows).
__global__ __launch_bounds__(256)
void k5_final(const float* __restrict__ x, float* __restrict__ out,
              const float* __restrict__ b3p){
  const int jt = blockIdx.x, b = blockIdx.y;
  const int t = threadIdx.x;
  __shared__ float4 s_s[64];
  __shared__ float  s_cf[Cdim];

  s_cf[t] = g_cf[b*Cdim + t];
  if (t < 64){
    const float b3 = b3p[0];
    int n = jt*256 + 4*t;
    float ah = g_ah[b*Hdim + (n>>7)];
    int w0 = n & 127;
    float4 t3 = *(const float4*)(g_t3s + (size_t)b*HW + n);
    float4 s;
    s.x = sigmoidf_((ah + g_aw[b*Wdim + w0+0])*t3.x + b3);
    s.y = sigmoidf_((ah + g_aw[b*Wdim + w0+1])*t3.y + b3);
    s.z = sigmoidf_((ah + g_aw[b*Wdim + w0+2])*t3.z + b3);
    s.w = sigmoidf_((ah + g_aw[b*Wdim + w0+3])*t3.w + b3);
    s_s[t] = s;
  }
  __syncthreads();

  const int c0 = t>>6, f4i = t&63;
  const float4 sv = s_s[f4i];
  const size_t base0 = (size_t)(b*Cdim)*4096 + jt*64 + f4i;
  const float4* x4 = (const float4*)x;
  float4* o4 = (float4*)out;
  #pragma unroll 4
  for (int it=0; it<64; it++){
    int c = it*4 + c0;
    float cf = s_cf[c];
    size_t idx = base0 + (size_t)c*4096;
    float4 xv = __ldcs(&x4[idx]);
    float4 o;
    o.x = fmaf(sv.x, cf, xv.x);
    o.y = fmaf(sv.y, cf, xv.y);
    o.z = fmaf(sv.z, cf, xv.z);
    o.w = fmaf(sv.w, cf, xv.w);
    __stcs(&o4[idx], o);
  }
}

// ---------------- launch ----------------
extern "C" void kernel_launch(void* const* d_in, const int* in_sizes, int n_in,
                              void* d_out, int out_size){
  const float* x  = (const float*)d_in[0];
  const float* vw = (const float*)d_in[1];
  const float* vb = (const float*)d_in[2];
  const float* kw = (const float*)d_in[3];
  const float* kb = (const float*)d_in[4];
  const float* w1 = (const float*)d_in[5];
  const float* b1 = (const float*)d_in[6];
  const float* w2 = (const float*)d_in[7];
  const float* b2 = (const float*)d_in[8];
  const float* w3 = (const float*)d_in[9];
  const float* b3 = (const float*)d_in[10];
  float* out = (float*)d_out;

  k0a<<<16,256>>>(vw, w3);                              // #1
  k0b<<<1,256>>>(vb, w3);                               // #2
  kdummy<<<1,32>>>();                                   // #3
  k1_main<<<dim3(NTT,Bdim),256>>>(x, kw, kb, w1, b1);   // #4 (profiled)
  k2b_attn<<<Bdim,384>>>(w1, b1, w2, b2);
  k2c_xk<<<dim3(Bdim,8),256>>>();
  k2d_cf<<<dim3(Bdim,8),256>>>(vw, vb);
  k5_final<<<dim3(64,Bdim),256>>>(x, out, b3);
}

// round 11
// speedup vs baseline: 1.1688x; 1.1688x over previous
#include <cuda_runtime.h>
#include <cfloat>
#include <math.h>

#define Cdim 256
#define Hdim 128
#define Wdim 128
#define HW   16384
#define Bdim 8
#define NTT  256        // tiles per batch: (row, half), 64 px each

// ---------------- scratch (device globals) ----------------
__device__ float g_up[16*Cdim];          // partial u
__device__ float g_u[Cdim];              // v_w^T w3
__device__ float g_t3bias;               // w3 . v_b
__device__ float g_t3s[Bdim*HW];         // t3 per pixel
__device__ float g_Mt[Bdim*NTT];
__device__ float g_Zt[Bdim*NTT];
__device__ float g_hpm[Bdim*NTT];        // per-tile h max partial
__device__ float g_hps[Bdim*NTT];        // per-tile h sum partial
__device__ float g_wpm[Bdim*NTT*64];     // per-tile column max partial
__device__ float g_wps[Bdim*NTT*64];     // per-tile column sum partial
__device__ float g_xkp[Bdim*NTT*Cdim];   // per-tile unnormalized xk partial
__device__ float g_ah[Bdim*Hdim];
__device__ float g_aw[Bdim*Wdim];
__device__ float g_cf[Bdim*Cdim];        // channel_fea

// ---------------- helpers ----------------
__device__ __forceinline__ float warpMax(float v){
  #pragma unroll
  for (int o=16;o;o>>=1) v = fmaxf(v, __shfl_xor_sync(0xffffffffu, v, o));
  return v;
}
__device__ __forceinline__ float warpSum(float v){
  #pragma unroll
  for (int o=16;o;o>>=1) v += __shfl_xor_sync(0xffffffffu, v, o);
  return v;
}
__device__ __forceinline__ float sigmoidf_(float x){ return 1.f/(1.f+expf(-x)); }

// ---------------- K0a: partial u (16 blocks) ----------------
__global__ __launch_bounds__(256)
void k0a(const float* __restrict__ vw, const float* __restrict__ w3){
  const int g = blockIdx.x, t = threadIdx.x;
  float u = 0.f;
  #pragma unroll
  for (int oo=0;oo<16;oo++){
    int o = 16*g + oo;
    u = fmaf(__ldg(&w3[o]), vw[o*Cdim + t], u);
  }
  g_up[g*Cdim + t] = u;
}

// ---------------- K0b: combine u + parallel t3bias ----------------
__global__ __launch_bounds__(256)
void k0b(const float* __restrict__ vb, const float* __restrict__ w3){
  const int t = threadIdx.x, warp = t>>5, lane = t&31;
  __shared__ float s_red[8];
  float u = 0.f;
  #pragma unroll
  for (int g=0;g<16;g++) u += g_up[g*Cdim + t];
  g_u[t] = u;
  float p = w3[t]*vb[t];
  p = warpSum(p);
  if (lane==0) s_red[warp] = p;
  __syncthreads();
  if (t==0){
    float tb = 0.f;
    #pragma unroll
    for (int r=0;r<8;r++) tb += s_red[r];
    g_t3bias = tb;
  }
}

// ---------------- K1: fused main pass (R9 winner config) ----------------
// grid (NTT, Bdim), 256 thr = 8 warps. Tile = 64 px (half row) x 256 ch.
// Warp w: channels [32w,32w+32); lane: c_off=lane>>4, f4i=lane&15.
__global__ __launch_bounds__(256)
void k1_main(const float* __restrict__ x, const float* __restrict__ kwp,
             const float* __restrict__ kbp,
             const float* __restrict__ w1, const float* __restrict__ b1){
  __shared__ float  s_kw[Cdim], s_u[Cdim];
  __shared__ float4 s_lp[8*32], s_tp[8*32], s_pm[8*32], s_ps[8*32]; // 16 KB
  __shared__ float4 s_e[16];
  __shared__ float  s_acc[256*17];                                  // 17 KB

  const int jt = blockIdx.x, b = blockIdx.y;
  const int row = jt>>1, half = jt&1;
  const int t = threadIdx.x, w = t>>5, lane = t&31;
  const int c_off = lane>>4, f4i = lane&15;

  s_kw[t] = kwp[t];
  s_u[t]  = g_u[t];
  __syncthreads();

  const float* xb = x + ((size_t)(b*Cdim + 32*w + c_off))*HW
                      + row*Wdim + half*64 + 4*f4i;

  // ---- pass A: load tile into registers + accumulate partials ----
  float4 xv[16];
  float4 aL = make_float4(0,0,0,0), aT = make_float4(0,0,0,0);
  float4 pm = make_float4(-FLT_MAX,-FLT_MAX,-FLT_MAX,-FLT_MAX);
  float4 ps = make_float4(0,0,0,0);
  #pragma unroll
  for (int k=0;k<16;k++){
    xv[k] = *(const float4*)(xb + (size_t)(2*k)*HW);
  }
  #pragma unroll
  for (int k=0;k<16;k++){
    float4 v = xv[k];
    int c = 32*w + 2*k + c_off;
    float kw = s_kw[c], uc = s_u[c];
    aL.x = fmaf(kw, v.x, aL.x); aL.y = fmaf(kw, v.y, aL.y);
    aL.z = fmaf(kw, v.z, aL.z); aL.w = fmaf(kw, v.w, aL.w);
    aT.x = fmaf(uc, v.x, aT.x); aT.y = fmaf(uc, v.y, aT.y);
    aT.z = fmaf(uc, v.z, aT.z); aT.w = fmaf(uc, v.w, aT.w);
    pm.x = fmaxf(pm.x, v.x); pm.y = fmaxf(pm.y, v.y);
    pm.z = fmaxf(pm.z, v.z); pm.w = fmaxf(pm.w, v.w);
    ps.x += v.x; ps.y += v.y; ps.z += v.z; ps.w += v.w;
  }
  s_lp[w*32+lane] = aL; s_tp[w*32+lane] = aT;
  s_pm[w*32+lane] = pm; s_ps[w*32+lane] = ps;
  __syncthreads();

  // ---- warp 0: per-pixel combine, t3, pools, softmax stats ----
  if (w == 0){
    const bool valid = (lane < 16);
    float hm = -FLT_MAX, hs = 0.f, lm = -FLT_MAX;
    float4 l = make_float4(0,0,0,0);
    if (valid){
      float4 tv = make_float4(0,0,0,0);
      float4 cm = make_float4(-FLT_MAX,-FLT_MAX,-FLT_MAX,-FLT_MAX);
      float4 cs = make_float4(0,0,0,0);
      #pragma unroll
      for (int i=0;i<16;i++){
        int idx = (i>>1)*32 + (i&1)*16 + lane;
        float4 a = s_lp[idx], bb = s_tp[idx];
        float4 m = s_pm[idx], ss = s_ps[idx];
        l.x += a.x; l.y += a.y; l.z += a.z; l.w += a.w;
        tv.x += bb.x; tv.y += bb.y; tv.z += bb.z; tv.w += bb.w;
        cm.x = fmaxf(cm.x,m.x); cm.y = fmaxf(cm.y,m.y);
        cm.z = fmaxf(cm.z,m.z); cm.w = fmaxf(cm.w,m.w);
        cs.x += ss.x; cs.y += ss.y; cs.z += ss.z; cs.w += ss.w;
      }
      const float kb = kbp[0], tb = g_t3bias;
      l.x += kb; l.y += kb; l.z += kb; l.w += kb;
      tv.x += tb; tv.y += tb; tv.z += tb; tv.w += tb;
      *(float4*)(g_t3s + (size_t)b*HW + row*Wdim + half*64 + 4*lane) = tv;
      *(float4*)(g_wpm + ((size_t)(b*NTT+jt))*64 + 4*lane) = cm;
      *(float4*)(g_wps + ((size_t)(b*NTT+jt))*64 + 4*lane) = cs;
      hm = fmaxf(fmaxf(cm.x,cm.y), fmaxf(cm.z,cm.w));
      hs = cs.x+cs.y+cs.z+cs.w;
      lm = fmaxf(fmaxf(l.x,l.y), fmaxf(l.z,l.w));
    }
    float M  = warpMax(lm);
    float hM = warpMax(hm);
    float hS = warpSum(hs);
    float4 e = make_float4(0,0,0,0);
    if (valid){
      e.x = expf(l.x-M); e.y = expf(l.y-M); e.z = expf(l.z-M); e.w = expf(l.w-M);
      s_e[lane] = e;
    }
    float z = warpSum(e.x+e.y+e.z+e.w);
    if (lane==0){
      g_Mt[b*NTT+jt] = M; g_Zt[b*NTT+jt] = z;
      g_hpm[b*NTT+jt] = hM; g_hps[b*NTT+jt] = hS;
    }
  }
  __syncthreads();

  // ---- pass B: xk partials from registers; transpose-reduce ----
  float4 ev = s_e[f4i];
  #pragma unroll
  for (int k=0;k<16;k++){
    int c = 32*w + 2*k + c_off;
    float4 v = xv[k];
    float acc = v.x*ev.x + v.y*ev.y;
    acc = fmaf(v.z, ev.z, acc); acc = fmaf(v.w, ev.w, acc);
    s_acc[c*17 + f4i] = acc;
  }
  __syncthreads();
  float xk = 0.f;
  #pragma unroll
  for (int i=0;i<16;i++) xk += s_acc[t*17 + i];
  g_xkp[((size_t)(b*NTT+jt))*Cdim + t] = xk;
}

// ---------------- K2: merged per-batch combine (attn + alpha + xk + cf) ----
// grid (Bdim), 512 thr = 16 warps.
__global__ __launch_bounds__(512)
void k2_combine(const float* __restrict__ vw, const float* __restrict__ vb,
                const float* __restrict__ w1, const float* __restrict__ b1,
                const float* __restrict__ w2, const float* __restrict__ b2){
  const int b = blockIdx.x, t = threadIdx.x;
  const int warp = t>>5, lane = t&31;
  __shared__ float s_m[256], s_s[256];
  __shared__ float s_alpha[NTT], s_xk[Cdim], s_xk2[Cdim], s_red[8];
  __shared__ float sM, sZ;

  // --- phase A: attentions ---
  if (t < 256){
    // w pools: coalesced sweep; col(f) = f&127 under f = t + 256*i
    const size_t base = (size_t)b*NTT*64;
    float m = -FLT_MAX, s = 0.f;
    #pragma unroll 16
    for (int i=0;i<64;i++){
      size_t idx = base + t + 256*i;
      m = fmaxf(m, g_wpm[idx]);
      s += g_wps[idx];
    }
    s_m[t] = m; s_s[t] = s;
  } else if (t < 384){
    int r = t - 256;
    float m = fmaxf(g_hpm[b*NTT + 2*r], g_hpm[b*NTT + 2*r + 1]);
    float s = g_hps[b*NTT + 2*r] + g_hps[b*NTT + 2*r + 1];
    g_ah[b*Hdim + r] = sigmoidf_(w1[0]*m + w1[1]*(s*(1.f/32768.f)) + b1[0]);
  }
  __syncthreads();
  if (t < 128){
    float m = fmaxf(s_m[t], s_m[t+128]);
    float s = s_s[t] + s_s[t+128];
    g_aw[b*Wdim + t] = sigmoidf_(w2[0]*m + w2[1]*(s*(1.f/32768.f)) + b2[0]);
  }

  // --- phase B: alpha over 256 tiles (threads 0..255) ---
  float m = (t < 256) ? g_Mt[b*NTT + t] : -FLT_MAX;
  float mm = warpMax(m);
  if (lane==0 && warp < 8) s_red[warp] = mm;
  __syncthreads();
  if (t==0){
    float M = s_red[0];
    #pragma unroll
    for (int r=1;r<8;r++) M = fmaxf(M, s_red[r]);
    sM = M;
  }
  __syncthreads();
  float ze = (t < 256) ? g_Zt[b*NTT + t]*expf(m - sM) : 0.f;
  float zz = warpSum(ze);
  if (lane==0 && warp < 8) s_red[warp] = zz;
  __syncthreads();
  if (t==0){
    float Z = 0.f;
    #pragma unroll
    for (int r=0;r<8;r++) Z += s_red[r];
    sZ = Z;
  }
  __syncthreads();
  if (t < 256) s_alpha[t] = expf(m - sM)/sZ;
  __syncthreads();

  // --- phase C: xk[c] = sum_j alpha[j]*xkp[j][c]; two halves of j ---
  {
    const int part = t>>8, c = t&255;
    const size_t base = ((size_t)b*NTT + part*128)*Cdim + c;
    float acc = 0.f;
    #pragma unroll 8
    for (int j=0;j<128;j++)
      acc = fmaf(g_xkp[base + (size_t)j*Cdim], s_alpha[part*128 + j], acc);
    if (part==0) s_xk[c] = acc; else s_xk2[c] = acc;
  }
  __syncthreads();
  if (t < 256) s_xk[t] += s_xk2[t];
  __syncthreads();

  // --- phase D: cf = vw @ xk + vb; warp per 16 outputs ---
  #pragma unroll 1
  for (int oo=0;oo<16;oo++){
    int tout = warp*16 + oo;
    const float4* vr = (const float4*)(vw + (size_t)tout*Cdim) + lane;
    float4 v0 = vr[0], v1 = vr[32];
    const float* xk0 = s_xk + 4*lane;
    float acc = v0.x*xk0[0] + v0.y*xk0[1];
    acc = fmaf(v0.z, xk0[2], acc); acc = fmaf(v0.w, xk0[3], acc);
    acc = fmaf(v1.x, xk0[128], acc); acc = fmaf(v1.y, xk0[129], acc);
    acc = fmaf(v1.z, xk0[130], acc); acc = fmaf(v1.w, xk0[131], acc);
    acc = warpSum(acc);
    if (lane==0) g_cf[b*Cdim + tout] = acc + vb[tout];
  }
}

// ---------------- K5: epilogue, channel-split for occupancy ----------------
// grid (64, 2, Bdim), 256 thr. Block: 128 channels x 256 px (2 rows).
__global__ __launch_bounds__(256)
void k5_final(const float* __restrict__ x, float* __restrict__ out,
              const float* __restrict__ b3p){
  const int jt = blockIdx.x, ch = blockIdx.y, b = blockIdx.z;
  const int t = threadIdx.x;
  __shared__ float4 s_s[64];
  __shared__ float  s_cf[128];

  if (t < 128) s_cf[t] = g_cf[b*Cdim + ch*128 + t];
  if (t >= 128 && t < 192){
    const float b3 = b3p[0];
    int li = t - 128;
    int n = jt*256 + 4*li;
    float ah = g_ah[b*Hdim + (n>>7)];
    int w0 = n & 127;
    float4 t3 = *(const float4*)(g_t3s + (size_t)b*HW + n);
    float4 s;
    s.x = sigmoidf_((ah + g_aw[b*Wdim + w0+0])*t3.x + b3);
    s.y = sigmoidf_((ah + g_aw[b*Wdim + w0+1])*t3.y + b3);
    s.z = sigmoidf_((ah + g_aw[b*Wdim + w0+2])*t3.z + b3);
    s.w = sigmoidf_((ah + g_aw[b*Wdim + w0+3])*t3.w + b3);
    s_s[li] = s;
  }
  __syncthreads();

  const int c0 = t>>6, f4i = t&63;
  const float4 sv = s_s[f4i];
  const size_t base0 = (size_t)(b*Cdim + ch*128)*4096 + jt*64 + f4i;
  const float4* x4 = (const float4*)x;
  float4* o4 = (float4*)out;
  #pragma unroll 8
  for (int it=0; it<32; it++){
    int c = it*4 + c0;
    float cf = s_cf[c];
    size_t idx = base0 + (size_t)c*4096;
    float4 xv = __ldcs(&x4[idx]);
    float4 o;
    o.x = fmaf(sv.x, cf, xv.x);
    o.y = fmaf(sv.y, cf, xv.y);
    o.z = fmaf(sv.z, cf, xv.z);
    o.w = fmaf(sv.w, cf, xv.w);
    __stcs(&o4[idx], o);
  }
}

// ---------------- launch ----------------
extern "C" void kernel_launch(void* const* d_in, const int* in_sizes, int n_in,
                              void* d_out, int out_size){
  const float* x  = (const float*)d_in[0];
  const float* vw = (const float*)d_in[1];
  const float* vb = (const float*)d_in[2];
  const float* kw = (const float*)d_in[3];
  const float* kb = (const float*)d_in[4];
  const float* w1 = (const float*)d_in[5];
  const float* b1 = (const float*)d_in[6];
  const float* w2 = (const float*)d_in[7];
  const float* b2 = (const float*)d_in[8];
  const float* w3 = (const float*)d_in[9];
  const float* b3 = (const float*)d_in[10];
  float* out = (float*)d_out;

  k0a<<<16,256>>>(vw, w3);                              // #1
  k0b<<<1,256>>>(vb, w3);                               // #2
  k1_main<<<dim3(NTT,Bdim),256>>>(x, kw, kb, w1, b1);   // #3
  k2_combine<<<Bdim,512>>>(vw, vb, w1, b1, w2, b2);     // #4 (profiled)
  k5_final<<<dim3(64,2,Bdim),256>>>(x, out, b3);        // #5
}

// round 13
// speedup vs baseline: 1.2247x; 1.0478x over previous
#include <cuda_runtime.h>
#include <cfloat>
#include <math.h>

#define Cdim 256
#define Hdim 128
#define Wdim 128
#define HW   16384
#define Bdim 8
#define NTT  256        // tiles per batch: (row, half), 64 px each

// ---------------- scratch (device globals) ----------------
__device__ float g_up[16*Cdim];          // partial u
__device__ float g_u[Cdim];              // v_w^T w3
__device__ float g_t3bias;               // w3 . v_b
__device__ float g_t3s[Bdim*HW];         // t3 per pixel
__device__ float g_Mt[Bdim*NTT];
__device__ float g_Zt[Bdim*NTT];
__device__ float g_alpha[Bdim*NTT];      // softmax tile weights
__device__ float g_hpm[Bdim*NTT];        // per-tile h max partial
__device__ float g_hps[Bdim*NTT];        // per-tile h sum partial
__device__ float g_wpm[Bdim*NTT*64];     // per-tile column max partial
__device__ float g_wps[Bdim*NTT*64];     // per-tile column sum partial
__device__ float g_xkp[Bdim*NTT*Cdim];   // per-tile unnormalized xk partial
__device__ float g_xk[Bdim*Cdim];        // combined xk
__device__ float g_ah[Bdim*Hdim];
__device__ float g_aw[Bdim*Wdim];
__device__ float g_cf[Bdim*Cdim];        // channel_fea

// ---------------- helpers ----------------
__device__ __forceinline__ float warpMax(float v){
  #pragma unroll
  for (int o=16;o;o>>=1) v = fmaxf(v, __shfl_xor_sync(0xffffffffu, v, o));
  return v;
}
__device__ __forceinline__ float warpSum(float v){
  #pragma unroll
  for (int o=16;o;o>>=1) v += __shfl_xor_sync(0xffffffffu, v, o);
  return v;
}
__device__ __forceinline__ float sigmoidf_(float x){ return 1.f/(1.f+expf(-x)); }

// ---------------- K0a: partial u (16 blocks) ----------------
__global__ __launch_bounds__(256)
void k0a(const float* __restrict__ vw, const float* __restrict__ w3){
  const int g = blockIdx.x, t = threadIdx.x;
  float u = 0.f;
  #pragma unroll
  for (int oo=0;oo<16;oo++){
    int o = 16*g + oo;
    u = fmaf(__ldg(&w3[o]), vw[o*Cdim + t], u);
  }
  g_up[g*Cdim + t] = u;
}

// ---------------- K0b: combine u + parallel t3bias ----------------
__global__ __launch_bounds__(256)
void k0b(const float* __restrict__ vb, const float* __restrict__ w3){
  const int t = threadIdx.x, warp = t>>5, lane = t&31;
  __shared__ float s_red[8];
  float u = 0.f;
  #pragma unroll
  for (int g=0;g<16;g++) u += g_up[g*Cdim + t];
  g_u[t] = u;
  float p = w3[t]*vb[t];
  p = warpSum(p);
  if (lane==0) s_red[warp] = p;
  __syncthreads();
  if (t==0){
    float tb = 0.f;
    #pragma unroll
    for (int r=0;r<8;r++) tb += s_red[r];
    g_t3bias = tb;
  }
}

// ---------------- K1: fused main pass (R9 winner config) ----------------
// grid (NTT, Bdim), 256 thr = 8 warps. Tile = 64 px (half row) x 256 ch.
__global__ __launch_bounds__(256)
void k1_main(const float* __restrict__ x, const float* __restrict__ kwp,
             const float* __restrict__ kbp,
             const float* __restrict__ w1, const float* __restrict__ b1){
  __shared__ float  s_kw[Cdim], s_u[Cdim];
  __shared__ float4 s_lp[8*32], s_tp[8*32], s_pm[8*32], s_ps[8*32]; // 16 KB
  __shared__ float4 s_e[16];
  __shared__ float  s_acc[256*17];                                  // 17 KB

  const int jt = blockIdx.x, b = blockIdx.y;
  const int row = jt>>1, half = jt&1;
  const int t = threadIdx.x, w = t>>5, lane = t&31;
  const int c_off = lane>>4, f4i = lane&15;

  s_kw[t] = kwp[t];
  s_u[t]  = g_u[t];
  __syncthreads();

  const float* xb = x + ((size_t)(b*Cdim + 32*w + c_off))*HW
                      + row*Wdim + half*64 + 4*f4i;

  // ---- pass A: load tile into registers + accumulate partials ----
  float4 xv[16];
  float4 aL = make_float4(0,0,0,0), aT = make_float4(0,0,0,0);
  float4 pm = make_float4(-FLT_MAX,-FLT_MAX,-FLT_MAX,-FLT_MAX);
  float4 ps = make_float4(0,0,0,0);
  #pragma unroll
  for (int k=0;k<16;k++){
    xv[k] = *(const float4*)(xb + (size_t)(2*k)*HW);
  }
  #pragma unroll
  for (int k=0;k<16;k++){
    float4 v = xv[k];
    int c = 32*w + 2*k + c_off;
    float kw = s_kw[c], uc = s_u[c];
    aL.x = fmaf(kw, v.x, aL.x); aL.y = fmaf(kw, v.y, aL.y);
    aL.z = fmaf(kw, v.z, aL.z); aL.w = fmaf(kw, v.w, aL.w);
    aT.x = fmaf(uc, v.x, aT.x); aT.y = fmaf(uc, v.y, aT.y);
    aT.z = fmaf(uc, v.z, aT.z); aT.w = fmaf(uc, v.w, aT.w);
    pm.x = fmaxf(pm.x, v.x); pm.y = fmaxf(pm.y, v.y);
    pm.z = fmaxf(pm.z, v.z); pm.w = fmaxf(pm.w, v.w);
    ps.x += v.x; ps.y += v.y; ps.z += v.z; ps.w += v.w;
  }
  s_lp[w*32+lane] = aL; s_tp[w*32+lane] = aT;
  s_pm[w*32+lane] = pm; s_ps[w*32+lane] = ps;
  __syncthreads();

  // ---- warp 0: per-pixel combine, t3, pools, softmax stats ----
  if (w == 0){
    const bool valid = (lane < 16);
    float hm = -FLT_MAX, hs = 0.f, lm = -FLT_MAX;
    float4 l = make_float4(0,0,0,0);
    if (valid){
      float4 tv = make_float4(0,0,0,0);
      float4 cm = make_float4(-FLT_MAX,-FLT_MAX,-FLT_MAX,-FLT_MAX);
      float4 cs = make_float4(0,0,0,0);
      #pragma unroll
      for (int i=0;i<16;i++){
        int idx = (i>>1)*32 + (i&1)*16 + lane;
        float4 a = s_lp[idx], bb = s_tp[idx];
        float4 m = s_pm[idx], ss = s_ps[idx];
        l.x += a.x; l.y += a.y; l.z += a.z; l.w += a.w;
        tv.x += bb.x; tv.y += bb.y; tv.z += bb.z; tv.w += bb.w;
        cm.x = fmaxf(cm.x,m.x); cm.y = fmaxf(cm.y,m.y);
        cm.z = fmaxf(cm.z,m.z); cm.w = fmaxf(cm.w,m.w);
        cs.x += ss.x; cs.y += ss.y; cs.z += ss.z; cs.w += ss.w;
      }
      const float kb = kbp[0], tb = g_t3bias;
      l.x += kb; l.y += kb; l.z += kb; l.w += kb;
      tv.x += tb; tv.y += tb; tv.z += tb; tv.w += tb;
      *(float4*)(g_t3s + (size_t)b*HW + row*Wdim + half*64 + 4*lane) = tv;
      *(float4*)(g_wpm + ((size_t)(b*NTT+jt))*64 + 4*lane) = cm;
      *(float4*)(g_wps + ((size_t)(b*NTT+jt))*64 + 4*lane) = cs;
      hm = fmaxf(fmaxf(cm.x,cm.y), fmaxf(cm.z,cm.w));
      hs = cs.x+cs.y+cs.z+cs.w;
      lm = fmaxf(fmaxf(l.x,l.y), fmaxf(l.z,l.w));
    }
    float M  = warpMax(lm);
    float hM = warpMax(hm);
    float hS = warpSum(hs);
    float4 e = make_float4(0,0,0,0);
    if (valid){
      e.x = expf(l.x-M); e.y = expf(l.y-M); e.z = expf(l.z-M); e.w = expf(l.w-M);
      s_e[lane] = e;
    }
    float z = warpSum(e.x+e.y+e.z+e.w);
    if (lane==0){
      g_Mt[b*NTT+jt] = M; g_Zt[b*NTT+jt] = z;
      g_hpm[b*NTT+jt] = hM; g_hps[b*NTT+jt] = hS;
    }
  }
  __syncthreads();

  // ---- pass B: xk partials from registers; transpose-reduce ----
  float4 ev = s_e[f4i];
  #pragma unroll
  for (int k=0;k<16;k++){
    int c = 32*w + 2*k + c_off;
    float4 v = xv[k];
    float acc = v.x*ev.x + v.y*ev.y;
    acc = fmaf(v.z, ev.z, acc); acc = fmaf(v.w, ev.w, acc);
    s_acc[c*17 + f4i] = acc;
  }
  __syncthreads();
  float xk = 0.f;
  #pragma unroll
  for (int i=0;i<16;i++) xk += s_acc[t*17 + i];
  g_xkp[((size_t)(b*NTT+jt))*Cdim + t] = xk;
}

// ---------------- K2a: attentions + alpha ----------------
// grid (Bdim, 2), 256 thr. y=0: w-pools. y=1: h-pools + alpha.
__global__ __launch_bounds__(256)
void k2a_attn(const float* __restrict__ w1, const float* __restrict__ b1,
              const float* __restrict__ w2, const float* __restrict__ b2){
  const int b = blockIdx.x, t = threadIdx.x;
  const int warp = t>>5, lane = t&31;

  if (blockIdx.y == 0){
    // w pools: coalesced sweep; col(f) = f&127 under f = t + 256*i
    __shared__ float s_m[256], s_s[256];
    const size_t base = (size_t)b*NTT*64;
    float m = -FLT_MAX, s = 0.f;
    #pragma unroll 16
    for (int i=0;i<64;i++){
      size_t idx = base + t + 256*i;
      m = fmaxf(m, g_wpm[idx]);
      s += g_wps[idx];
    }
    s_m[t] = m; s_s[t] = s;
    __syncthreads();
    if (t < 128){
      float mm = fmaxf(s_m[t], s_m[t+128]);
      float ss = s_s[t] + s_s[t+128];
      g_aw[b*Wdim + t] = sigmoidf_(w2[0]*mm + w2[1]*(ss*(1.f/32768.f)) + b2[0]);
    }
  } else {
    // h pools + alpha
    __shared__ float s_red[8];
    __shared__ float sM, sZ;
    if (t < 128){
      float m = fmaxf(g_hpm[b*NTT + 2*t], g_hpm[b*NTT + 2*t + 1]);
      float s = g_hps[b*NTT + 2*t] + g_hps[b*NTT + 2*t + 1];
      g_ah[b*Hdim + t] = sigmoidf_(w1[0]*m + w1[1]*(s*(1.f/32768.f)) + b1[0]);
    }
    float m = g_Mt[b*NTT + t];
    float mm = warpMax(m);
    if (lane==0) s_red[warp] = mm;
    __syncthreads();
    if (t==0){
      float M = s_red[0];
      #pragma unroll
      for (int r=1;r<8;r++) M = fmaxf(M, s_red[r]);
      sM = M;
    }
    __syncthreads();
    float ze = g_Zt[b*NTT + t]*expf(m - sM);
    float zz = warpSum(ze);
    if (lane==0) s_red[warp] = zz;
    __syncthreads();
    if (t==0){
      float Z = 0.f;
      #pragma unroll
      for (int r=0;r<8;r++) Z += s_red[r];
      sZ = Z;
    }
    __syncthreads();
    g_alpha[b*NTT + t] = expf(m - sM)/sZ;
  }
}

// ---------------- K2c: xk combine ----------------
// grid (Bdim, 8), 256 thr. Block covers 32 channels x all 256 tiles.
__global__ __launch_bounds__(256)
void k2c_xk(){
  const int b = blockIdx.x, cg = blockIdx.y;
  const int t = threadIdx.x;
  const int jsub = t>>5, c32 = t&31;
  __shared__ float s_alpha[NTT], s_part[8][33];

  s_alpha[t] = g_alpha[b*NTT + t];
  __syncthreads();

  const int c = cg*32 + c32;
  float acc = 0.f;
  #pragma unroll 8
  for (int k=0;k<32;k++){
    int j = jsub + 8*k;
    acc = fmaf(g_xkp[((size_t)(b*NTT+j))*Cdim + c], s_alpha[j], acc);
  }
  s_part[jsub][c32] = acc;
  __syncthreads();
  if (t < 32){
    float xk = 0.f;
    #pragma unroll
    for (int r=0;r<8;r++) xk += s_part[r][t];
    g_xk[b*Cdim + cg*32 + t] = xk;
  }
}

// ---------------- K2d: cf = vw @ xk + vb, vw read once chip-wide ----------
// grid (32), 256 thr = 8 warps. Warp = one output row; all 8 batches inside.
__global__ __launch_bounds__(256)
void k2d_cf(const float* __restrict__ vw, const float* __restrict__ vb){
  const int blk = blockIdx.x;
  const int t = threadIdx.x, warp = t>>5, lane = t&31;
  __shared__ float4 s_xk[Bdim*64];     // 8 batches x 256 floats

  #pragma unroll
  for (int i=t;i<Bdim*64;i+=256) s_xk[i] = ((const float4*)g_xk)[i];
  __syncthreads();

  const int tout = blk*8 + warp;
  const float4* vr = (const float4*)(vw + (size_t)tout*Cdim);
  float4 v0 = vr[lane], v1 = vr[32+lane];
  float bias = __ldg(&vb[tout]);
  #pragma unroll
  for (int b=0;b<Bdim;b++){
    float4 k0 = s_xk[b*64 + lane], k1 = s_xk[b*64 + 32 + lane];
    float acc = v0.x*k0.x + v0.y*k0.y;
    acc = fmaf(v0.z, k0.z, acc); acc = fmaf(v0.w, k0.w, acc);
    acc = fmaf(v1.x, k1.x, acc); acc = fmaf(v1.y, k1.y, acc);
    acc = fmaf(v1.z, k1.z, acc); acc = fmaf(v1.w, k1.w, acc);
    acc = warpSum(acc);
    if (lane==0) g_cf[b*Cdim + tout] = acc + bias;
  }
}

// ---------------- K5: epilogue, channel-split for occupancy ----------------
// grid (64, 2, Bdim), 256 thr. Block: 128 channels x 256 px (2 rows).
__global__ __launch_bounds__(256)
void k5_final(const float* __restrict__ x, float* __restrict__ out,
              const float* __restrict__ b3p){
  const int jt = blockIdx.x, ch = blockIdx.y, b = blockIdx.z;
  const int t = threadIdx.x;
  __shared__ float4 s_s[64];
  __shared__ float  s_cf[128];

  if (t < 128) s_cf[t] = g_cf[b*Cdim + ch*128 + t];
  if (t >= 128 && t < 192){
    const float b3 = b3p[0];
    int li = t - 128;
    int n = jt*256 + 4*li;
    float ah = g_ah[b*Hdim + (n>>7)];
    int w0 = n & 127;
    float4 t3 = *(const float4*)(g_t3s + (size_t)b*HW + n);
    float4 s;
    s.x = sigmoidf_((ah + g_aw[b*Wdim + w0+0])*t3.x + b3);
    s.y = sigmoidf_((ah + g_aw[b*Wdim + w0+1])*t3.y + b3);
    s.z = sigmoidf_((ah + g_aw[b*Wdim + w0+2])*t3.z + b3);
    s.w = sigmoidf_((ah + g_aw[b*Wdim + w0+3])*t3.w + b3);
    s_s[li] = s;
  }
  __syncthreads();

  const int c0 = t>>6, f4i = t&63;
  const float4 sv = s_s[f4i];
  const size_t base0 = (size_t)(b*Cdim + ch*128)*4096 + jt*64 + f4i;
  const float4* x4 = (const float4*)x;
  float4* o4 = (float4*)out;
  #pragma unroll 8
  for (int it=0; it<32; it++){
    int c = it*4 + c0;
    float cf = s_cf[c];
    size_t idx = base0 + (size_t)c*4096;
    float4 xv = __ldcs(&x4[idx]);
    float4 o;
    o.x = fmaf(sv.x, cf, xv.x);
    o.y = fmaf(sv.y, cf, xv.y);
    o.z = fmaf(sv.z, cf, xv.z);
    o.w = fmaf(sv.w, cf, xv.w);
    __stcs(&o4[idx], o);
  }
}

// ---------------- launch ----------------
extern "C" void kernel_launch(void* const* d_in, const int* in_sizes, int n_in,
                              void* d_out, int out_size){
  const float* x  = (const float*)d_in[0];
  const float* vw = (const float*)d_in[1];
  const float* vb = (const float*)d_in[2];
  const float* kw = (const float*)d_in[3];
  const float* kb = (const float*)d_in[4];
  const float* w1 = (const float*)d_in[5];
  const float* b1 = (const float*)d_in[6];
  const float* w2 = (const float*)d_in[7];
  const float* b2 = (const float*)d_in[8];
  const float* w3 = (const float*)d_in[9];
  const float* b3 = (const float*)d_in[10];
  float* out = (float*)d_out;

  k0a<<<16,256>>>(vw, w3);                              // #1
  k0b<<<1,256>>>(vb, w3);                               // #2
  k1_main<<<dim3(NTT,Bdim),256>>>(x, kw, kb, w1, b1);   // #3
  k2a_attn<<<dim3(Bdim,2),256>>>(w1, b1, w2, b2);       // #4 (profiled)
  k2c_xk<<<dim3(Bdim,8),256>>>();                       // #5
  k2d_cf<<<32,256>>>(vw, vb);                           // #6
  k5_final<<<dim3(64,2,Bdim),256>>>(x, out, b3);        // #7
}

// round 14
// speedup vs baseline: 1.3833x; 1.1295x over previous
#include <cuda_runtime.h>
#include <cfloat>
#include <math.h>

#define Cdim 256
#define Hdim 128
#define Wdim 128
#define HW   16384
#define Bdim 8
#define NTT  256        // tiles per batch: (row, half), 64 px each

// ---------------- scratch (device globals) ----------------
__device__ float g_up[16*Cdim];          // partial u
__device__ float g_u[Cdim];              // v_w^T w3
__device__ float g_t3bias;               // w3 . v_b
__device__ float g_t3s[Bdim*HW];         // t3 per pixel
__device__ float g_Mt[Bdim*NTT];
__device__ float g_Zt[Bdim*NTT];
__device__ float g_hpm[Bdim*NTT];        // per-tile h max partial
__device__ float g_hps[Bdim*NTT];        // per-tile h sum partial
__device__ float g_wpm[Bdim*NTT*64];     // per-tile column max partial
__device__ float g_wps[Bdim*NTT*64];     // per-tile column sum partial
__device__ float g_xkp[Bdim*NTT*Cdim];   // per-tile unnormalized xk partial
__device__ float g_xk[Bdim*Cdim];        // combined xk
__device__ float g_ah[Bdim*Hdim];
__device__ float g_aw[Bdim*Wdim];
__device__ float g_cf[Bdim*Cdim];        // channel_fea

// ---------------- helpers ----------------
__device__ __forceinline__ float warpMax(float v){
  #pragma unroll
  for (int o=16;o;o>>=1) v = fmaxf(v, __shfl_xor_sync(0xffffffffu, v, o));
  return v;
}
__device__ __forceinline__ float warpSum(float v){
  #pragma unroll
  for (int o=16;o;o>>=1) v += __shfl_xor_sync(0xffffffffu, v, o);
  return v;
}
__device__ __forceinline__ float sigmoidf_(float x){ return 1.f/(1.f+expf(-x)); }

// ---------------- K0a: partial u (16 blocks) ----------------
__global__ __launch_bounds__(256)
void k0a(const float* __restrict__ vw, const float* __restrict__ w3){
  const int g = blockIdx.x, t = threadIdx.x;
  float u = 0.f;
  #pragma unroll
  for (int oo=0;oo<16;oo++){
    int o = 16*g + oo;
    u = fmaf(__ldg(&w3[o]), vw[o*Cdim + t], u);
  }
  g_up[g*Cdim + t] = u;
}

// ---------------- K0b: combine u + parallel t3bias ----------------
__global__ __launch_bounds__(256)
void k0b(const float* __restrict__ vb, const float* __restrict__ w3){
  const int t = threadIdx.x, warp = t>>5, lane = t&31;
  __shared__ float s_red[8];
  float u = 0.f;
  #pragma unroll
  for (int g=0;g<16;g++) u += g_up[g*Cdim + t];
  g_u[t] = u;
  float p = w3[t]*vb[t];
  p = warpSum(p);
  if (lane==0) s_red[warp] = p;
  __syncthreads();
  if (t==0){
    float tb = 0.f;
    #pragma unroll
    for (int r=0;r<8;r++) tb += s_red[r];
    g_t3bias = tb;
  }
}

// ---------------- K1: fused main pass (R9 winner config) ----------------
// grid (NTT, Bdim), 256 thr = 8 warps. Tile = 64 px (half row) x 256 ch.
__global__ __launch_bounds__(256)
void k1_main(const float* __restrict__ x, const float* __restrict__ kwp,
             const float* __restrict__ kbp,
             const float* __restrict__ w1, const float* __restrict__ b1){
  __shared__ float  s_kw[Cdim], s_u[Cdim];
  __shared__ float4 s_lp[8*32], s_tp[8*32], s_pm[8*32], s_ps[8*32]; // 16 KB
  __shared__ float4 s_e[16];
  __shared__ float  s_acc[256*17];                                  // 17 KB

  const int jt = blockIdx.x, b = blockIdx.y;
  const int row = jt>>1, half = jt&1;
  const int t = threadIdx.x, w = t>>5, lane = t&31;
  const int c_off = lane>>4, f4i = lane&15;

  s_kw[t] = kwp[t];
  s_u[t]  = g_u[t];
  __syncthreads();

  const float* xb = x + ((size_t)(b*Cdim + 32*w + c_off))*HW
                      + row*Wdim + half*64 + 4*f4i;

  // ---- pass A: load tile into registers + accumulate partials ----
  float4 xv[16];
  float4 aL = make_float4(0,0,0,0), aT = make_float4(0,0,0,0);
  float4 pm = make_float4(-FLT_MAX,-FLT_MAX,-FLT_MAX,-FLT_MAX);
  float4 ps = make_float4(0,0,0,0);
  #pragma unroll
  for (int k=0;k<16;k++){
    xv[k] = *(const float4*)(xb + (size_t)(2*k)*HW);
  }
  #pragma unroll
  for (int k=0;k<16;k++){
    float4 v = xv[k];
    int c = 32*w + 2*k + c_off;
    float kw = s_kw[c], uc = s_u[c];
    aL.x = fmaf(kw, v.x, aL.x); aL.y = fmaf(kw, v.y, aL.y);
    aL.z = fmaf(kw, v.z, aL.z); aL.w = fmaf(kw, v.w, aL.w);
    aT.x = fmaf(uc, v.x, aT.x); aT.y = fmaf(uc, v.y, aT.y);
    aT.z = fmaf(uc, v.z, aT.z); aT.w = fmaf(uc, v.w, aT.w);
    pm.x = fmaxf(pm.x, v.x); pm.y = fmaxf(pm.y, v.y);
    pm.z = fmaxf(pm.z, v.z); pm.w = fmaxf(pm.w, v.w);
    ps.x += v.x; ps.y += v.y; ps.z += v.z; ps.w += v.w;
  }
  s_lp[w*32+lane] = aL; s_tp[w*32+lane] = aT;
  s_pm[w*32+lane] = pm; s_ps[w*32+lane] = ps;
  __syncthreads();

  // ---- warp 0: per-pixel combine, t3, pools, softmax stats ----
  if (w == 0){
    const bool valid = (lane < 16);
    float hm = -FLT_MAX, hs = 0.f, lm = -FLT_MAX;
    float4 l = make_float4(0,0,0,0);
    if (valid){
      float4 tv = make_float4(0,0,0,0);
      float4 cm = make_float4(-FLT_MAX,-FLT_MAX,-FLT_MAX,-FLT_MAX);
      float4 cs = make_float4(0,0,0,0);
      #pragma unroll
      for (int i=0;i<16;i++){
        int idx = (i>>1)*32 + (i&1)*16 + lane;
        float4 a = s_lp[idx], bb = s_tp[idx];
        float4 m = s_pm[idx], ss = s_ps[idx];
        l.x += a.x; l.y += a.y; l.z += a.z; l.w += a.w;
        tv.x += bb.x; tv.y += bb.y; tv.z += bb.z; tv.w += bb.w;
        cm.x = fmaxf(cm.x,m.x); cm.y = fmaxf(cm.y,m.y);
        cm.z = fmaxf(cm.z,m.z); cm.w = fmaxf(cm.w,m.w);
        cs.x += ss.x; cs.y += ss.y; cs.z += ss.z; cs.w += ss.w;
      }
      const float kb = kbp[0], tb = g_t3bias;
      l.x += kb; l.y += kb; l.z += kb; l.w += kb;
      tv.x += tb; tv.y += tb; tv.z += tb; tv.w += tb;
      *(float4*)(g_t3s + (size_t)b*HW + row*Wdim + half*64 + 4*lane) = tv;
      *(float4*)(g_wpm + ((size_t)(b*NTT+jt))*64 + 4*lane) = cm;
      *(float4*)(g_wps + ((size_t)(b*NTT+jt))*64 + 4*lane) = cs;
      hm = fmaxf(fmaxf(cm.x,cm.y), fmaxf(cm.z,cm.w));
      hs = cs.x+cs.y+cs.z+cs.w;
      lm = fmaxf(fmaxf(l.x,l.y), fmaxf(l.z,l.w));
    }
    float M  = warpMax(lm);
    float hM = warpMax(hm);
    float hS = warpSum(hs);
    float4 e = make_float4(0,0,0,0);
    if (valid){
      e.x = expf(l.x-M); e.y = expf(l.y-M); e.z = expf(l.z-M); e.w = expf(l.w-M);
      s_e[lane] = e;
    }
    float z = warpSum(e.x+e.y+e.z+e.w);
    if (lane==0){
      g_Mt[b*NTT+jt] = M; g_Zt[b*NTT+jt] = z;
      g_hpm[b*NTT+jt] = hM; g_hps[b*NTT+jt] = hS;
    }
  }
  __syncthreads();

  // ---- pass B: xk partials from registers; transpose-reduce ----
  float4 ev = s_e[f4i];
  #pragma unroll
  for (int k=0;k<16;k++){
    int c = 32*w + 2*k + c_off;
    float4 v = xv[k];
    float acc = v.x*ev.x + v.y*ev.y;
    acc = fmaf(v.z, ev.z, acc); acc = fmaf(v.w, ev.w, acc);
    s_acc[c*17 + f4i] = acc;
  }
  __syncthreads();
  float xk = 0.f;
  #pragma unroll
  for (int i=0;i<16;i++) xk += s_acc[t*17 + i];
  g_xkp[((size_t)(b*NTT+jt))*Cdim + t] = xk;
}

// ---------------- K2: merged glue (w/h attn + alpha + xk), wide ----------
// grid (Bdim, 9), 512 thr.
//  y=0: w-pools (512-thr split sweep) + h-pools.
//  y=1..8: alpha recompute + xk for 32 channels (16-way j-parallel).
__global__ __launch_bounds__(512)
void k2_glue(const float* __restrict__ w1, const float* __restrict__ b1,
             const float* __restrict__ w2, const float* __restrict__ b2){
  const int b = blockIdx.x, y = blockIdx.y;
  const int t = threadIdx.x, warp = t>>5, lane = t&31;

  if (y == 0){
    // ---- w pools: col(f) = f&127 under f = tt + 256*i; two i-halves ----
    __shared__ float s_m[512], s_s[512];
    const int tt = t & 255, part = t >> 8;
    const size_t base = (size_t)b*NTT*64;
    float m = -FLT_MAX, s = 0.f;
    #pragma unroll 16
    for (int i=part*32; i<part*32+32; i++){
      size_t idx = base + tt + 256*i;
      m = fmaxf(m, g_wpm[idx]);
      s += g_wps[idx];
    }
    s_m[t] = m; s_s[t] = s;
    __syncthreads();
    if (t < 128){
      float mm = fmaxf(fmaxf(s_m[t], s_m[t+128]), fmaxf(s_m[t+256], s_m[t+384]));
      float ss = s_s[t] + s_s[t+128] + s_s[t+256] + s_s[t+384];
      g_aw[b*Wdim + t] = sigmoidf_(w2[0]*mm + w2[1]*(ss*(1.f/32768.f)) + b2[0]);
    } else if (t >= 256 && t < 384){
      int r = t - 256;
      float m2 = fmaxf(g_hpm[b*NTT + 2*r], g_hpm[b*NTT + 2*r + 1]);
      float s2 = g_hps[b*NTT + 2*r] + g_hps[b*NTT + 2*r + 1];
      g_ah[b*Hdim + r] = sigmoidf_(w1[0]*m2 + w1[1]*(s2*(1.f/32768.f)) + b1[0]);
    }
  } else {
    // ---- alpha (local recompute) + xk for channels [32(y-1), 32y) ----
    const int cg = y - 1;
    __shared__ float s_alpha[NTT], s_red[8], s_part[16][33];
    __shared__ float sM, sZ;

    float m = (t < 256) ? g_Mt[b*NTT + t] : -FLT_MAX;
    float mm = warpMax(m);
    if (lane==0 && warp < 8) s_red[warp] = mm;
    __syncthreads();
    if (t==0){
      float M = s_red[0];
      #pragma unroll
      for (int r=1;r<8;r++) M = fmaxf(M, s_red[r]);
      sM = M;
    }
    __syncthreads();
    float ze = (t < 256) ? g_Zt[b*NTT + t]*expf(m - sM) : 0.f;
    float zz = warpSum(ze);
    if (lane==0 && warp < 8) s_red[warp] = zz;
    __syncthreads();
    if (t==0){
      float Z = 0.f;
      #pragma unroll
      for (int r=0;r<8;r++) Z += s_red[r];
      sZ = Z;
    }
    __syncthreads();
    if (t < 256) s_alpha[t] = expf(m - sM)/sZ;
    __syncthreads();

    const int jsub = t>>5, c32 = t&31;     // 16 j-slices x 32 channels
    const int c = cg*32 + c32;
    float acc = 0.f;
    #pragma unroll 8
    for (int k=0;k<16;k++){
      int j = jsub + 16*k;
      acc = fmaf(g_xkp[((size_t)(b*NTT+j))*Cdim + c], s_alpha[j], acc);
    }
    s_part[jsub][c32] = acc;
    __syncthreads();
    if (t < 32){
      float xk = 0.f;
      #pragma unroll
      for (int r=0;r<16;r++) xk += s_part[r][t];
      g_xk[b*Cdim + cg*32 + t] = xk;
    }
  }
}

// ---------------- K2d: cf = vw @ xk + vb, vw read once chip-wide ----------
// grid (32), 256 thr = 8 warps. Warp = one output row; all 8 batches inside.
__global__ __launch_bounds__(256)
void k2d_cf(const float* __restrict__ vw, const float* __restrict__ vb){
  const int blk = blockIdx.x;
  const int t = threadIdx.x, warp = t>>5, lane = t&31;
  __shared__ float4 s_xk[Bdim*64];     // 8 batches x 256 floats

  #pragma unroll
  for (int i=t;i<Bdim*64;i+=256) s_xk[i] = ((const float4*)g_xk)[i];
  __syncthreads();

  const int tout = blk*8 + warp;
  const float4* vr = (const float4*)(vw + (size_t)tout*Cdim);
  float4 v0 = vr[lane], v1 = vr[32+lane];
  float bias = __ldg(&vb[tout]);
  #pragma unroll
  for (int b=0;b<Bdim;b++){
    float4 k0 = s_xk[b*64 + lane], k1 = s_xk[b*64 + 32 + lane];
    float acc = v0.x*k0.x + v0.y*k0.y;
    acc = fmaf(v0.z, k0.z, acc); acc = fmaf(v0.w, k0.w, acc);
    acc = fmaf(v1.x, k1.x, acc); acc = fmaf(v1.y, k1.y, acc);
    acc = fmaf(v1.z, k1.z, acc); acc = fmaf(v1.w, k1.w, acc);
    acc = warpSum(acc);
    if (lane==0) g_cf[b*Cdim + tout] = acc + bias;
  }
}

// ---------------- K5: epilogue, channel-split for occupancy ----------------
// grid (64, 2, Bdim), 256 thr. Block: 128 channels x 256 px (2 rows).
__global__ __launch_bounds__(256)
void k5_final(const float* __restrict__ x, float* __restrict__ out,
              const float* __restrict__ b3p){
  const int jt = blockIdx.x, ch = blockIdx.y, b = blockIdx.z;
  const int t = threadIdx.x;
  __shared__ float4 s_s[64];
  __shared__ float  s_cf[128];

  if (t < 128) s_cf[t] = g_cf[b*Cdim + ch*128 + t];
  if (t >= 128 && t < 192){
    const float b3 = b3p[0];
    int li = t - 128;
    int n = jt*256 + 4*li;
    float ah = g_ah[b*Hdim + (n>>7)];
    int w0 = n & 127;
    float4 t3 = *(const float4*)(g_t3s + (size_t)b*HW + n);
    float4 s;
    s.x = sigmoidf_((ah + g_aw[b*Wdim + w0+0])*t3.x + b3);
    s.y = sigmoidf_((ah + g_aw[b*Wdim + w0+1])*t3.y + b3);
    s.z = sigmoidf_((ah + g_aw[b*Wdim + w0+2])*t3.z + b3);
    s.w = sigmoidf_((ah + g_aw[b*Wdim + w0+3])*t3.w + b3);
    s_s[li] = s;
  }
  __syncthreads();

  const int c0 = t>>6, f4i = t&63;
  const float4 sv = s_s[f4i];
  const size_t base0 = (size_t)(b*Cdim + ch*128)*4096 + jt*64 + f4i;
  const float4* x4 = (const float4*)x;
  float4* o4 = (float4*)out;
  #pragma unroll 8
  for (int it=0; it<32; it++){
    int c = it*4 + c0;
    float cf = s_cf[c];
    size_t idx = base0 + (size_t)c*4096;
    float4 xv = __ldcs(&x4[idx]);
    float4 o;
    o.x = fmaf(sv.x, cf, xv.x);
    o.y = fmaf(sv.y, cf, xv.y);
    o.z = fmaf(sv.z, cf, xv.z);
    o.w = fmaf(sv.w, cf, xv.w);
    __stcs(&o4[idx], o);
  }
}

// ---------------- launch ----------------
extern "C" void kernel_launch(void* const* d_in, const int* in_sizes, int n_in,
                              void* d_out, int out_size){
  const float* x  = (const float*)d_in[0];
  const float* vw = (const float*)d_in[1];
  const float* vb = (const float*)d_in[2];
  const float* kw = (const float*)d_in[3];
  const float* kb = (const float*)d_in[4];
  const float* w1 = (const float*)d_in[5];
  const float* b1 = (const float*)d_in[6];
  const float* w2 = (const float*)d_in[7];
  const float* b2 = (const float*)d_in[8];
  const float* w3 = (const float*)d_in[9];
  const float* b3 = (const float*)d_in[10];
  float* out = (float*)d_out;

  k0a<<<16,256>>>(vw, w3);                              // #1
  k0b<<<1,256>>>(vb, w3);                               // #2
  k1_main<<<dim3(NTT,Bdim),256>>>(x, kw, kb, w1, b1);   // #3
  k2_glue<<<dim3(Bdim,9),512>>>(w1, b1, w2, b2);        // #4 (profiled)
  k2d_cf<<<32,256>>>(vw, vb);                           // #5
  k5_final<<<dim3(64,2,Bdim),256>>>(x, out, b3);        // #6
}